// round 4
// baseline (speedup 1.0000x reference)
#include <cuda_runtime.h>
#include <cstdint>
#include <cstdio>

// ---------------- scratch (static device globals; no allocation) ----------------
__device__ float g_tu[2 * 100000 * 64];
__device__ float g_ti[2 * 100000 * 64];
__device__ float g_t [200000 * 64];
__device__ float g_s [800000 * 64];          // per-cell s buffers, cumulative rows
__device__ float2 g_wT[5 * 2048];            // packed tf32 T-weight frags
__device__ float2 g_wI[5 * 2048];            // packed tf32 I-weight frags
// CSR scratch
__device__ int  g_cnt[800000];
__device__ int  g_ptr[800000];
__device__ int  g_cur[800000];
__device__ int  g_bsum[256];
__device__ int2 g_ecv[6400000];              // (col_local, val_bits) sorted by global row

// ---------------- helpers ----------------
__device__ __forceinline__ unsigned long long fma2(unsigned long long a,
                                                   unsigned long long b,
                                                   unsigned long long c) {
    unsigned long long d;
    asm("fma.rn.f32x2 %0, %1, %2, %3;" : "=l"(d) : "l"(a), "l"(b), "l"(c));
    return d;
}
__device__ __forceinline__ unsigned long long pk2(float x, float y) {
    unsigned long long r;
    asm("mov.b64 %0, {%1, %2};" : "=l"(r) : "f"(x), "f"(y));
    return r;
}
__device__ __forceinline__ float2 up2(unsigned long long v) {
    float2 r;
    asm("mov.b64 {%0, %1}, %2;" : "=f"(r.x), "=f"(r.y) : "l"(v));
    return r;
}
__device__ __forceinline__ unsigned int tf32c(float f) {
    unsigned int r;
    asm("cvt.rna.tf32.f32 %0, %1;" : "=r"(r) : "f"(f));
    return r;
}
__device__ __forceinline__ void mma_tf32(float c[4],
                                         unsigned int a0, unsigned int a1,
                                         unsigned int a2, unsigned int a3,
                                         unsigned int b0, unsigned int b1) {
    asm("mma.sync.aligned.m16n8k8.row.col.f32.tf32.tf32.f32 "
        "{%0,%1,%2,%3}, {%4,%5,%6,%7}, {%8,%9}, {%0,%1,%2,%3};"
        : "+f"(c[0]), "+f"(c[1]), "+f"(c[2]), "+f"(c[3])
        : "r"(a0), "r"(a1), "r"(a2), "r"(a3), "r"(b0), "r"(b1));
}

// ---------------- descriptor tables ----------------
struct GCell {
    const float* xA; const float* xB; int nA; int n;
    const float2* wT; const float2* wI;
    const float* Tb; const float* Ib;
    float* outA; float* outB; float* s;
};
struct GTab { int off[6]; GCell c[5]; };

struct ECell { const int* rows; const int* cols; const float* vals; int nnz; int rowbase; };
struct ETab { int off[6]; ECell c[5]; };

struct RCell { const float* sIn; float* outA; float* outB; int nA; };
struct RTab { int rb[6]; RCell c[5]; };

// ---------------- weight fragment packer ----------------
__global__ __launch_bounds__(256) void pack_weights(
    const float* tw0, const float* iw0, const float* tw1, const float* iw1,
    const float* tw2, const float* iw2, const float* tw3, const float* iw3,
    const float* tw4, const float* iw4, float2* wT, float2* wI)
{
    int idx = blockIdx.x * 256 + threadIdx.x;
    if (idx >= 5 * 2048) return;
    int c = idx >> 11;
    int kt = (idx >> 8) & 7;
    int nt = (idx >> 5) & 7;
    int l = idx & 31;
    const float* tw; const float* iw;
    switch (c) {
        case 0: tw = tw0; iw = iw0; break;
        case 1: tw = tw1; iw = iw1; break;
        case 2: tw = tw2; iw = iw2; break;
        case 3: tw = tw3; iw = iw3; break;
        default: tw = tw4; iw = iw4; break;
    }
    int k0 = kt * 8 + (l & 3);
    int n0 = nt * 8 + (l >> 2);
    float2 ot, oi;
    ot.x = __uint_as_float(tf32c(tw[k0 * 64 + n0]));
    ot.y = __uint_as_float(tf32c(tw[(k0 + 4) * 64 + n0]));
    oi.x = __uint_as_float(tf32c(iw[k0 * 64 + n0]));
    oi.y = __uint_as_float(tf32c(iw[(k0 + 4) * 64 + n0]));
    wT[idx] = ot;
    wI[idx] = oi;
}

// ---------------- fused dual GEMM (all 5 cells, one launch) ----------------
__global__ __launch_bounds__(128, 5) void gcn_gemm_all(GTab tab)
{
    __shared__ __align__(16) float sX[64 * 68];
    int b = blockIdx.x;
    int c = 0;
#pragma unroll
    for (int i = 1; i < 5; ++i) c += (b >= tab.off[i]);
    const GCell cl = tab.c[c];
    const int row0 = (b - tab.off[c]) * 64;
    const int tid = threadIdx.x;
    const int n = cl.n;

    for (int i = tid; i < 64 * 16; i += 128) {
        int r = i >> 4, c4 = i & 15;
        int gr = row0 + r;
        float4 v = make_float4(0.f, 0.f, 0.f, 0.f);
        if (gr < n) {
            const float* src = (gr < cl.nA) ? (cl.xA + (size_t)gr * 64)
                                            : (cl.xB + (size_t)(gr - cl.nA) * 64);
            v = *reinterpret_cast<const float4*>(src + c4 * 4);
        }
        *reinterpret_cast<float4*>(sX + r * 68 + c4 * 4) = v;
    }
    __syncthreads();

    const int wid = tid >> 5;
    const int lane = tid & 31;
    const int g = lane >> 2;
    const int t4 = lane & 3;
    const float* xr0 = sX + (wid * 16 + g) * 68;
    const float* xr1 = xr0 + 8 * 68;

    float xf0[8], xf1[8], xf2[8], xf3[8];
#pragma unroll
    for (int kt = 0; kt < 8; ++kt) {
        int c0 = kt * 8 + t4;
        xf0[kt] = xr0[c0];
        xf1[kt] = xr1[c0];
        xf2[kt] = xr0[c0 + 4];
        xf3[kt] = xr1[c0 + 4];
    }

    float acc[8][4];
#pragma unroll
    for (int nt = 0; nt < 8; ++nt)
#pragma unroll
        for (int i = 0; i < 4; ++i) acc[nt][i] = 0.f;

    // T phase
#pragma unroll
    for (int kt = 0; kt < 8; ++kt) {
        unsigned int a0 = tf32c(xf0[kt]), a1 = tf32c(xf1[kt]);
        unsigned int a2 = tf32c(xf2[kt]), a3 = tf32c(xf3[kt]);
        const float2* wr = cl.wT + kt * 256 + lane;
#pragma unroll
        for (int nt = 0; nt < 8; ++nt) {
            float2 w = wr[nt * 32];
            mma_tf32(acc[nt], a0, a1, a2, a3,
                     __float_as_uint(w.x), __float_as_uint(w.y));
        }
    }

    const int r0 = row0 + wid * 16 + g;
    const int r1 = r0 + 8;
    float* op0 = nullptr; float* op1 = nullptr;
    if (r0 < n) op0 = (r0 < cl.nA) ? (cl.outA + (size_t)r0 * 64)
                                   : (cl.outB + (size_t)(r0 - cl.nA) * 64);
    if (r1 < n) op1 = (r1 < cl.nA) ? (cl.outA + (size_t)r1 * 64)
                                   : (cl.outB + (size_t)(r1 - cl.nA) * 64);

#pragma unroll
    for (int nt = 0; nt < 8; ++nt) {
        int col = nt * 8 + 2 * t4;
        float tbx = cl.Tb[col], tby = cl.Tb[col + 1];
        if (op0) *reinterpret_cast<float2*>(op0 + col) =
            make_float2(acc[nt][0] + tbx, acc[nt][1] + tby);
        if (op1) *reinterpret_cast<float2*>(op1 + col) =
            make_float2(acc[nt][2] + tbx, acc[nt][3] + tby);
    }

    // Q phase
#pragma unroll
    for (int kt = 0; kt < 8; ++kt) {
        unsigned int q0 = tf32c(xf0[kt] * xf0[kt]), q1 = tf32c(xf1[kt] * xf1[kt]);
        unsigned int q2 = tf32c(xf2[kt] * xf2[kt]), q3 = tf32c(xf3[kt] * xf3[kt]);
        const float2* wr = cl.wI + kt * 256 + lane;
#pragma unroll
        for (int nt = 0; nt < 8; ++nt) {
            float2 w = wr[nt * 32];
            mma_tf32(acc[nt], q0, q1, q2, q3,
                     __float_as_uint(w.x), __float_as_uint(w.y));
        }
    }

#pragma unroll
    for (int nt = 0; nt < 8; ++nt) {
        int col = nt * 8 + 2 * t4;
        float sbx = cl.Tb[col] + cl.Ib[col];
        float sby = cl.Tb[col + 1] + cl.Ib[col + 1];
        if (r0 < n) *reinterpret_cast<float2*>(cl.s + (size_t)r0 * 64 + col) =
            make_float2(acc[nt][0] + sbx, acc[nt][1] + sby);
        if (r1 < n) *reinterpret_cast<float2*>(cl.s + (size_t)r1 * 64 + col) =
            make_float2(acc[nt][2] + sbx, acc[nt][3] + sby);
    }
}

// ---------------- CSR build ----------------
__global__ __launch_bounds__(256) void zero_cnt(int* cnt, int n) {
    int i = blockIdx.x * 256 + threadIdx.x;
    if (i < n) cnt[i] = 0;
}

__global__ __launch_bounds__(256) void edge_hist(ETab tab, int* __restrict__ cnt) {
    int b = blockIdx.x;
    int c = 0;
#pragma unroll
    for (int i = 1; i < 5; ++i) c += (b >= tab.off[i]);
    const ECell cl = tab.c[c];
    int base = (b - tab.off[c]) * 2048 + threadIdx.x;
#pragma unroll
    for (int k = 0; k < 8; ++k) {
        int e = base + k * 256;
        if (e < cl.nnz) atomicAdd(&cnt[cl.rowbase + __ldg(cl.rows + e)], 1);
    }
}

// scanA: 1024 threads, 4 elems each -> per-block exclusive prefix + block sums
__global__ __launch_bounds__(1024) void scanA(const int* __restrict__ cnt, int n,
                                              int* __restrict__ ptr, int* __restrict__ bsum) {
    __shared__ int sh[1024];
    int tid = threadIdx.x;
    int i0 = blockIdx.x * 4096 + tid * 4;
    int a0 = (i0 < n) ? cnt[i0] : 0;
    int a1 = (i0 + 1 < n) ? cnt[i0 + 1] : 0;
    int a2 = (i0 + 2 < n) ? cnt[i0 + 2] : 0;
    int a3 = (i0 + 3 < n) ? cnt[i0 + 3] : 0;
    int s1 = a0, s2 = s1 + a1, s3 = s2 + a2, s4 = s3 + a3;
    sh[tid] = s4;
    for (int off = 1; off < 1024; off <<= 1) {
        __syncthreads();
        int v = (tid >= off) ? sh[tid - off] : 0;
        __syncthreads();
        sh[tid] += v;
    }
    __syncthreads();
    int excl = sh[tid] - s4;
    if (i0 < n)     ptr[i0]     = excl;
    if (i0 + 1 < n) ptr[i0 + 1] = excl + s1;
    if (i0 + 2 < n) ptr[i0 + 2] = excl + s2;
    if (i0 + 3 < n) ptr[i0 + 3] = excl + s3;
    if (tid == 1023) bsum[blockIdx.x] = sh[1023];
}

__global__ __launch_bounds__(256) void scanB(int* __restrict__ bsum, int nb) {
    __shared__ int sh[256];
    int tid = threadIdx.x;
    int v = (tid < nb) ? bsum[tid] : 0;
    sh[tid] = v;
    for (int off = 1; off < 256; off <<= 1) {
        __syncthreads();
        int u = (tid >= off) ? sh[tid - off] : 0;
        __syncthreads();
        sh[tid] += u;
    }
    __syncthreads();
    if (tid < nb) bsum[tid] = sh[tid] - v;   // exclusive
}

__global__ __launch_bounds__(256) void scanC(int* __restrict__ ptr, int* __restrict__ cur,
                                             const int* __restrict__ bsum, int n) {
    int i = blockIdx.x * 256 + threadIdx.x;
    if (i < n) {
        int p = ptr[i] + bsum[i >> 12];
        ptr[i] = p;
        cur[i] = p;
    }
}

__global__ __launch_bounds__(256) void edge_scatter(ETab tab, int* __restrict__ cur,
                                                    int2* __restrict__ ecv) {
    int b = blockIdx.x;
    int c = 0;
#pragma unroll
    for (int i = 1; i < 5; ++i) c += (b >= tab.off[i]);
    const ECell cl = tab.c[c];
    int base = (b - tab.off[c]) * 2048 + threadIdx.x;
#pragma unroll
    for (int k = 0; k < 8; ++k) {
        int e = base + k * 256;
        if (e < cl.nnz) {
            int grow = cl.rowbase + __ldg(cl.rows + e);
            int pos = atomicAdd(&cur[grow], 1);
            ecv[pos] = make_int2(__ldg(cl.cols + e),
                                 __float_as_int(__ldg(cl.vals + e)));
        }
    }
}

// ---------------- CSR gather: out[row] += sum_e val_e * s[col_e] ----------------
// one warp per global row; lane owns 2 floats; edges broadcast via shfl.
__global__ __launch_bounds__(256) void csr_gather(RTab tab,
                                                  const int* __restrict__ ptr,
                                                  const int* __restrict__ cnt,
                                                  const int2* __restrict__ ecv) {
    int grow = blockIdx.x * 8 + (threadIdx.x >> 5);
    int lane = threadIdx.x & 31;
    if (grow >= tab.rb[5]) return;
    int c = 0;
#pragma unroll
    for (int i = 1; i < 5; ++i) c += (grow >= tab.rb[i]);
    const RCell cl = tab.c[c];
    int deg = __ldg(cnt + grow);
    if (deg == 0) return;
    int start = __ldg(ptr + grow);
    int lrow = grow - tab.rb[c];

    float accx = 0.f, accy = 0.f;
    for (int j0 = 0; j0 < deg; j0 += 32) {
        int idx = j0 + lane;
        int2 e = make_int2(0, 0);
        if (idx < deg) e = __ldg(ecv + start + idx);
        int m = min(32, deg - j0);
        for (int jj = 0; jj < m; ++jj) {
            int col = __shfl_sync(0xffffffffu, e.x, jj);
            float v = __int_as_float(__shfl_sync(0xffffffffu, e.y, jj));
            float2 sv = *reinterpret_cast<const float2*>(
                cl.sIn + (size_t)col * 64 + lane * 2);
            accx += v * sv.x;
            accy += v * sv.y;
        }
    }
    float* op = (lrow < cl.nA) ? (cl.outA + (size_t)lrow * 64)
                               : (cl.outB + (size_t)(lrow - cl.nA) * 64);
    float2 o = *reinterpret_cast<float2*>(op + lane * 2);
    o.x += accx; o.y += accy;
    *reinterpret_cast<float2*>(op + lane * 2) = o;
}

// ---------------- fused relation attention (u and i in one launch) ----------------
__global__ __launch_bounds__(256) void rel_att_both(
    const float* __restrict__ tu, const float* __restrict__ ti,
    const float* __restrict__ t, int U, int I,
    const float* __restrict__ uw1, const float* __restrict__ ub1, const float* __restrict__ uw2,
    const float* __restrict__ iw1, const float* __restrict__ ib1, const float* __restrict__ iw2,
    float* __restrict__ out_u, float* __restrict__ out_i)
{
    __shared__ __align__(16) unsigned long long sW[2][1024];
    __shared__ __align__(16) float zb[8][3][64];
    const int tid = threadIdx.x;
    const int lane = tid & 31;
    const int wid = tid >> 5;

    for (int i = tid; i < 1024; i += 256) {
        int m = i >> 5, h = i & 31;
        sW[0][i] = pk2(uw1[(2 * m) * 32 + h], uw1[(2 * m + 1) * 32 + h]);
        sW[1][i] = pk2(iw1[(2 * m) * 32 + h], iw1[(2 * m + 1) * 32 + h]);
    }
    __syncthreads();

    const int node = blockIdx.x * 8 + wid;
    if (node >= U + I) return;

    const float *z0, *z1, *z2, *b1, *w2;
    float* out;
    const unsigned long long* w;
    int m_;
    if (node < U) {
        m_ = node; z0 = tu; z1 = tu + (size_t)U * 64; z2 = t;
        b1 = ub1; w2 = uw2; out = out_u; w = sW[0];
    } else {
        m_ = node - U; z0 = ti; z1 = ti + (size_t)I * 64; z2 = t + (size_t)U * 64;
        b1 = ib1; w2 = iw2; out = out_i; w = sW[1];
    }
    const float b1v = b1[lane];
    const float w2v = w2[lane];

    size_t base = (size_t)m_ * 64;
    float za0 = z0[base + lane], za1 = z0[base + lane + 32];
    float zc0 = z1[base + lane], zc1 = z1[base + lane + 32];
    float zd0 = z2[base + lane], zd1 = z2[base + lane + 32];
    zb[wid][0][lane] = za0; zb[wid][0][lane + 32] = za1;
    zb[wid][1][lane] = zc0; zb[wid][1][lane + 32] = zc1;
    zb[wid][2][lane] = zd0; zb[wid][2][lane + 32] = zd1;
    __syncwarp();

    float wl[3];
#pragma unroll
    for (int jj = 0; jj < 3; ++jj) {
        const unsigned long long* zp =
            reinterpret_cast<const unsigned long long*>(zb[wid][jj]);
        unsigned long long acc0 = 0ULL, acc1 = 0ULL;   // 2 chains to break dep latency
#pragma unroll
        for (int m = 0; m < 16; ++m) {
            acc0 = fma2(zp[m],      w[m * 32 + lane],        acc0);
            acc1 = fma2(zp[m + 16], w[(m + 16) * 32 + lane], acc1);
        }
        float2 a = up2(acc0);
        float2 bq = up2(acc1);
        float cc = tanhf(a.x + a.y + bq.x + bq.y + b1v) * w2v;
#pragma unroll
        for (int o = 16; o; o >>= 1) cc += __shfl_xor_sync(0xffffffffu, cc, o);
        wl[jj] = cc;
    }
    float mx = fmaxf(wl[0], fmaxf(wl[1], wl[2]));
    float e0 = __expf(wl[0] - mx), e1 = __expf(wl[1] - mx), e2 = __expf(wl[2] - mx);
    float inv = 1.0f / (e0 + e1 + e2);
    float beta0 = e0 * inv, beta1 = e1 * inv, beta2 = e2 * inv;
    out[base + lane]      = beta0 * za0 + beta1 * zc0 + beta2 * zd0;
    out[base + lane + 32] = beta0 * za1 + beta1 * zc1 + beta2 * zd1;
}

// ---------------- host launcher ----------------
extern "C" void kernel_launch(void* const* d_in, const int* in_sizes, int n_in,
                              void* d_out, int out_size)
{
    const int*   u2i_idx  = (const int*)  d_in[0];
    const float* u2i_val  = (const float*)d_in[1];
    const int*   u2e_idx  = (const int*)  d_in[2];
    const float* u2e_val  = (const float*)d_in[3];
    const int*   i2e_idx  = (const int*)  d_in[4];
    const float* i2e_val  = (const float*)d_in[5];
    const float* u_feat   = (const float*)d_in[6];
    const float* i_feat   = (const float*)d_in[7];
    const float* u2e_feat = (const float*)d_in[8];
    const float* i2e_feat = (const float*)d_in[9];
    const float* Tw_u2i = (const float*)d_in[10];
    const float* Tb_u2i = (const float*)d_in[11];
    const float* Iw_u2i = (const float*)d_in[12];
    const float* Ib_u2i = (const float*)d_in[13];
    const float* Tw_u2e = (const float*)d_in[14];
    const float* Tb_u2e = (const float*)d_in[15];
    const float* Iw_u2e = (const float*)d_in[16];
    const float* Ib_u2e = (const float*)d_in[17];
    const float* Tw_i2e = (const float*)d_in[18];
    const float* Tb_i2e = (const float*)d_in[19];
    const float* Iw_i2e = (const float*)d_in[20];
    const float* Ib_i2e = (const float*)d_in[21];
    const float* uatt_w1 = (const float*)d_in[22];
    const float* uatt_b1 = (const float*)d_in[23];
    const float* uatt_w2 = (const float*)d_in[24];
    const float* iatt_w1 = (const float*)d_in[25];
    const float* iatt_b1 = (const float*)d_in[26];
    const float* iatt_w2 = (const float*)d_in[27];

    const int U = in_sizes[6] / 64;
    const int I = in_sizes[7] / 64;
    const int E = in_sizes[8] / (2 * 64);
    const int NNZ_UI = in_sizes[1];
    const int NNZ_E  = in_sizes[3] / 2;

    float *tu, *ti, *t, *s;
    float2 *wT, *wI;
    int *cnt, *ptr, *cur, *bsum;
    int2* ecv;
    cudaGetSymbolAddress((void**)&tu, g_tu);
    cudaGetSymbolAddress((void**)&ti, g_ti);
    cudaGetSymbolAddress((void**)&t,  g_t);
    cudaGetSymbolAddress((void**)&s,  g_s);
    cudaGetSymbolAddress((void**)&wT, g_wT);
    cudaGetSymbolAddress((void**)&wI, g_wI);
    cudaGetSymbolAddress((void**)&cnt, g_cnt);
    cudaGetSymbolAddress((void**)&ptr, g_ptr);
    cudaGetSymbolAddress((void**)&cur, g_cur);
    cudaGetSymbolAddress((void**)&bsum, g_bsum);
    cudaGetSymbolAddress((void**)&ecv, g_ecv);

    float* outp    = (float*)d_out;
    float* out_u   = outp;
    float* out_i   = outp + (size_t)U * 64;
    float* out_u2e = outp + (size_t)(U + I) * 64;
    float* out_i2e = out_u2e + (size_t)2 * E * 64;

    int ns[5]  = {U + E, U + E, I + E, I + E, U + I};
    int nAs[5] = {U, U, I, I, U + I};
    int rb[6];
    rb[0] = 0;
    for (int i = 0; i < 5; ++i) rb[i + 1] = rb[i] + ns[i];
    const int ntot = rb[5];

    // ---- CSR build (independent of GEMM) ----
    zero_cnt<<<(ntot + 255) / 256, 256>>>(cnt, ntot);

    ETab et;
    {
        const int* rws[5] = {u2e_idx, u2e_idx + (size_t)2 * NNZ_E,
                             i2e_idx, i2e_idx + (size_t)2 * NNZ_E, u2i_idx};
        const float* vls[5] = {u2e_val, u2e_val + NNZ_E,
                               i2e_val, i2e_val + NNZ_E, u2i_val};
        int nnzs[5] = {NNZ_E, NNZ_E, NNZ_E, NNZ_E, NNZ_UI};
        et.off[0] = 0;
        for (int i = 0; i < 5; ++i) {
            et.c[i].rows = rws[i];
            et.c[i].cols = rws[i] + nnzs[i];
            et.c[i].vals = vls[i];
            et.c[i].nnz = nnzs[i];
            et.c[i].rowbase = rb[i];
            et.off[i + 1] = et.off[i] + (nnzs[i] + 2047) / 2048;
        }
    }
    edge_hist<<<et.off[5], 256>>>(et, cnt);

    int nbA = (ntot + 4095) / 4096;
    scanA<<<nbA, 1024>>>(cnt, ntot, ptr, bsum);
    scanB<<<1, 256>>>(bsum, nbA);
    scanC<<<(ntot + 255) / 256, 256>>>(ptr, cur, bsum, ntot);

    edge_scatter<<<et.off[5], 256>>>(et, cur, ecv);

    // ---- GEMMs ----
    pack_weights<<<40, 256>>>(
        Tw_u2e, Iw_u2e, Tw_u2e + 4096, Iw_u2e + 4096,
        Tw_i2e, Iw_i2e, Tw_i2e + 4096, Iw_i2e + 4096,
        Tw_u2i, Iw_u2i, wT, wI);

    GTab gt;
    {
        const float* xAs[5] = {u_feat, u_feat, i_feat, i_feat, u_feat};
        const float* xBs[5] = {u2e_feat, u2e_feat + (size_t)E * 64,
                               i2e_feat, i2e_feat + (size_t)E * 64, i_feat};
        int gnAs[5] = {U, U, I, I, U};
        const float* Tbs[5] = {Tb_u2e, Tb_u2e + 64, Tb_i2e, Tb_i2e + 64, Tb_u2i};
        const float* Ibs[5] = {Ib_u2e, Ib_u2e + 64, Ib_i2e, Ib_i2e + 64, Ib_u2i};
        float* outAs[5] = {tu, tu + (size_t)U * 64, ti, ti + (size_t)I * 64, t};
        float* outBs[5] = {out_u2e, out_u2e + (size_t)E * 64,
                           out_i2e, out_i2e + (size_t)E * 64, t + (size_t)U * 64};
        gt.off[0] = 0;
        for (int i = 0; i < 5; ++i) {
            gt.c[i].xA = xAs[i]; gt.c[i].xB = xBs[i];
            gt.c[i].nA = gnAs[i]; gt.c[i].n = ns[i];
            gt.c[i].wT = wT + (size_t)i * 2048;
            gt.c[i].wI = wI + (size_t)i * 2048;
            gt.c[i].Tb = Tbs[i]; gt.c[i].Ib = Ibs[i];
            gt.c[i].outA = outAs[i]; gt.c[i].outB = outBs[i];
            gt.c[i].s = s + (size_t)rb[i] * 64;
            gt.off[i + 1] = gt.off[i] + (ns[i] + 63) / 64;
        }
    }
    gcn_gemm_all<<<gt.off[5], 128>>>(gt);

    // ---- gather ----
    RTab rt;
    {
        float* outAs[5] = {tu, tu + (size_t)U * 64, ti, ti + (size_t)I * 64, t};
        float* outBs[5] = {out_u2e, out_u2e + (size_t)E * 64,
                           out_i2e, out_i2e + (size_t)E * 64, t};
        for (int i = 0; i < 6; ++i) rt.rb[i] = rb[i];
        for (int i = 0; i < 5; ++i) {
            rt.c[i].sIn = s + (size_t)rb[i] * 64;
            rt.c[i].outA = outAs[i];
            rt.c[i].outB = outBs[i];
            rt.c[i].nA = nAs[i];
        }
    }
    csr_gather<<<(ntot + 7) / 8, 256>>>(rt, ptr, cnt, ecv);

    // ---- attention (fused u+i) ----
    rel_att_both<<<(U + I + 7) / 8, 256>>>(
        tu, ti, t, U, I,
        uatt_w1, uatt_b1, uatt_w2,
        iatt_w1, iatt_b1, iatt_w2,
        out_u, out_i);
}

// round 5
// speedup vs baseline: 1.2777x; 1.2777x over previous
#include <cuda_runtime.h>
#include <cstdint>
#include <cstdio>

// ---------------- scratch (static device globals; no allocation) ----------------
__device__ float g_tu[2 * 100000 * 64];
__device__ float g_ti[2 * 100000 * 64];
__device__ float g_t [200000 * 64];
__device__ float g_s [800000 * 64];          // per-cell s buffers, cumulative rows
__device__ float2 g_wT[5 * 2048];            // packed tf32 T-weight frags
__device__ float2 g_wI[5 * 2048];            // packed tf32 I-weight frags

// ---------------- helpers ----------------
__device__ __forceinline__ unsigned long long fma2(unsigned long long a,
                                                   unsigned long long b,
                                                   unsigned long long c) {
    unsigned long long d;
    asm("fma.rn.f32x2 %0, %1, %2, %3;" : "=l"(d) : "l"(a), "l"(b), "l"(c));
    return d;
}
__device__ __forceinline__ unsigned long long pk2(float x, float y) {
    unsigned long long r;
    asm("mov.b64 %0, {%1, %2};" : "=l"(r) : "f"(x), "f"(y));
    return r;
}
__device__ __forceinline__ float2 up2(unsigned long long v) {
    float2 r;
    asm("mov.b64 {%0, %1}, %2;" : "=f"(r.x), "=f"(r.y) : "l"(v));
    return r;
}
__device__ __forceinline__ void red4(float* p, float a, float b, float c, float d) {
    asm volatile("red.global.add.v4.f32 [%0], {%1, %2, %3, %4};"
                 :: "l"(p), "f"(a), "f"(b), "f"(c), "f"(d) : "memory");
}
__device__ __forceinline__ unsigned int tf32c(float f) {
    unsigned int r;
    asm("cvt.rna.tf32.f32 %0, %1;" : "=r"(r) : "f"(f));
    return r;
}
__device__ __forceinline__ void mma_tf32(float c[4],
                                         unsigned int a0, unsigned int a1,
                                         unsigned int a2, unsigned int a3,
                                         unsigned int b0, unsigned int b1) {
    asm("mma.sync.aligned.m16n8k8.row.col.f32.tf32.tf32.f32 "
        "{%0,%1,%2,%3}, {%4,%5,%6,%7}, {%8,%9}, {%0,%1,%2,%3};"
        : "+f"(c[0]), "+f"(c[1]), "+f"(c[2]), "+f"(c[3])
        : "r"(a0), "r"(a1), "r"(a2), "r"(a3), "r"(b0), "r"(b1));
}

// ---------------- descriptor tables ----------------
struct GCell {
    const float* xA; const float* xB; int nA; int n;
    const float2* wT; const float2* wI;
    const float* Tb; const float* Ib;
    float* outA; float* outB; float* s;
};
struct GTab { int off[6]; GCell c[5]; };

struct SCell {
    const int* rows; const int* cols; const float* vals; int nnz;
    const float* sIn; float* outA; int nA; float* outB;
};
struct STab { int off[6]; SCell c[5]; };

// ---------------- weight fragment packer ----------------
__global__ __launch_bounds__(256) void pack_weights(
    const float* tw0, const float* iw0, const float* tw1, const float* iw1,
    const float* tw2, const float* iw2, const float* tw3, const float* iw3,
    const float* tw4, const float* iw4, float2* wT, float2* wI)
{
    int idx = blockIdx.x * 256 + threadIdx.x;
    if (idx >= 5 * 2048) return;
    int c = idx >> 11;
    int kt = (idx >> 8) & 7;
    int nt = (idx >> 5) & 7;
    int l = idx & 31;
    const float* tw; const float* iw;
    switch (c) {
        case 0: tw = tw0; iw = iw0; break;
        case 1: tw = tw1; iw = iw1; break;
        case 2: tw = tw2; iw = iw2; break;
        case 3: tw = tw3; iw = iw3; break;
        default: tw = tw4; iw = iw4; break;
    }
    int k0 = kt * 8 + (l & 3);
    int n0 = nt * 8 + (l >> 2);
    float2 ot, oi;
    ot.x = __uint_as_float(tf32c(tw[k0 * 64 + n0]));
    ot.y = __uint_as_float(tf32c(tw[(k0 + 4) * 64 + n0]));
    oi.x = __uint_as_float(tf32c(iw[k0 * 64 + n0]));
    oi.y = __uint_as_float(tf32c(iw[(k0 + 4) * 64 + n0]));
    wT[idx] = ot;
    wI[idx] = oi;
}

// ---------------- fused dual GEMM (all 5 cells, one launch) ----------------
// Sequential T->Q phases share one accumulator: t = x@Tw+Tb written at midpoint,
// then Q-GEMM keeps accumulating -> s = t + x^2@Iw + Ib.
__global__ __launch_bounds__(128, 5) void gcn_gemm_all(GTab tab)
{
    __shared__ __align__(16) float sX[64 * 68];
    int b = blockIdx.x;
    int c = 0;
#pragma unroll
    for (int i = 1; i < 5; ++i) c += (b >= tab.off[i]);
    const GCell cl = tab.c[c];
    const int row0 = (b - tab.off[c]) * 64;
    const int tid = threadIdx.x;
    const int n = cl.n;

    for (int i = tid; i < 64 * 16; i += 128) {
        int r = i >> 4, c4 = i & 15;
        int gr = row0 + r;
        float4 v = make_float4(0.f, 0.f, 0.f, 0.f);
        if (gr < n) {
            const float* src = (gr < cl.nA) ? (cl.xA + (size_t)gr * 64)
                                            : (cl.xB + (size_t)(gr - cl.nA) * 64);
            v = *reinterpret_cast<const float4*>(src + c4 * 4);
        }
        *reinterpret_cast<float4*>(sX + r * 68 + c4 * 4) = v;
    }
    __syncthreads();

    const int wid = tid >> 5;
    const int lane = tid & 31;
    const int g = lane >> 2;
    const int t4 = lane & 3;
    const float* xr0 = sX + (wid * 16 + g) * 68;
    const float* xr1 = xr0 + 8 * 68;

    float xf0[8], xf1[8], xf2[8], xf3[8];
#pragma unroll
    for (int kt = 0; kt < 8; ++kt) {
        int c0 = kt * 8 + t4;
        xf0[kt] = xr0[c0];
        xf1[kt] = xr1[c0];
        xf2[kt] = xr0[c0 + 4];
        xf3[kt] = xr1[c0 + 4];
    }

    float acc[8][4];
#pragma unroll
    for (int nt = 0; nt < 8; ++nt)
#pragma unroll
        for (int i = 0; i < 4; ++i) acc[nt][i] = 0.f;

    // T phase
#pragma unroll
    for (int kt = 0; kt < 8; ++kt) {
        unsigned int a0 = tf32c(xf0[kt]), a1 = tf32c(xf1[kt]);
        unsigned int a2 = tf32c(xf2[kt]), a3 = tf32c(xf3[kt]);
        const float2* wr = cl.wT + kt * 256 + lane;
#pragma unroll
        for (int nt = 0; nt < 8; ++nt) {
            float2 w = wr[nt * 32];
            mma_tf32(acc[nt], a0, a1, a2, a3,
                     __float_as_uint(w.x), __float_as_uint(w.y));
        }
    }

    const int r0 = row0 + wid * 16 + g;
    const int r1 = r0 + 8;
    float* op0 = nullptr; float* op1 = nullptr;
    if (r0 < n) op0 = (r0 < cl.nA) ? (cl.outA + (size_t)r0 * 64)
                                   : (cl.outB + (size_t)(r0 - cl.nA) * 64);
    if (r1 < n) op1 = (r1 < cl.nA) ? (cl.outA + (size_t)r1 * 64)
                                   : (cl.outB + (size_t)(r1 - cl.nA) * 64);

    // midpoint epilogue: write t = acc + Tb
#pragma unroll
    for (int nt = 0; nt < 8; ++nt) {
        int col = nt * 8 + 2 * t4;
        float tbx = cl.Tb[col], tby = cl.Tb[col + 1];
        if (op0) *reinterpret_cast<float2*>(op0 + col) =
            make_float2(acc[nt][0] + tbx, acc[nt][1] + tby);
        if (op1) *reinterpret_cast<float2*>(op1 + col) =
            make_float2(acc[nt][2] + tbx, acc[nt][3] + tby);
    }

    // Q phase (accumulates on top of T)
#pragma unroll
    for (int kt = 0; kt < 8; ++kt) {
        unsigned int q0 = tf32c(xf0[kt] * xf0[kt]), q1 = tf32c(xf1[kt] * xf1[kt]);
        unsigned int q2 = tf32c(xf2[kt] * xf2[kt]), q3 = tf32c(xf3[kt] * xf3[kt]);
        const float2* wr = cl.wI + kt * 256 + lane;
#pragma unroll
        for (int nt = 0; nt < 8; ++nt) {
            float2 w = wr[nt * 32];
            mma_tf32(acc[nt], q0, q1, q2, q3,
                     __float_as_uint(w.x), __float_as_uint(w.y));
        }
    }

    // final epilogue: write s = acc + Tb + Ib
#pragma unroll
    for (int nt = 0; nt < 8; ++nt) {
        int col = nt * 8 + 2 * t4;
        float sbx = cl.Tb[col] + cl.Ib[col];
        float sby = cl.Tb[col + 1] + cl.Ib[col + 1];
        if (r0 < n) *reinterpret_cast<float2*>(cl.s + (size_t)r0 * 64 + col) =
            make_float2(acc[nt][0] + sbx, acc[nt][1] + sby);
        if (r1 < n) *reinterpret_cast<float2*>(cl.s + (size_t)r1 * 64 + col) =
            make_float2(acc[nt][2] + sbx, acc[nt][3] + sby);
    }
}

// ---------------- fused edge scatter (all 5 cells, one launch) ----------------
// 16 lanes per edge, 2 edges per thread, coalesced gathers + red.v4.
__global__ __launch_bounds__(256) void spmm_all(STab tab)
{
    int b = blockIdx.x;
    int c = 0;
#pragma unroll
    for (int i = 1; i < 5; ++i) c += (b >= tab.off[i]);
    const SCell cl = tab.c[c];
    long long t = (long long)(b - tab.off[c]) * 256 + threadIdx.x;
    int l = (int)(t & 15);
    int e0 = (int)(t >> 4) * 2;
    if (e0 >= cl.nnz) return;

    int r0 = __ldg(cl.rows + e0);
    int c0 = __ldg(cl.cols + e0);
    float v0 = __ldg(cl.vals + e0);
    bool has1 = (e0 + 1) < cl.nnz;
    int r1 = r0, c1 = c0;
    float v1 = 0.f;
    if (has1) {
        r1 = __ldg(cl.rows + e0 + 1);
        c1 = __ldg(cl.cols + e0 + 1);
        v1 = __ldg(cl.vals + e0 + 1);
    }
    float4 s0 = *reinterpret_cast<const float4*>(cl.sIn + (size_t)c0 * 64 + l * 4);
    float4 s1 = *reinterpret_cast<const float4*>(cl.sIn + (size_t)c1 * 64 + l * 4);

    float* p0 = ((r0 < cl.nA) ? (cl.outA + (size_t)r0 * 64)
                              : (cl.outB + (size_t)(r0 - cl.nA) * 64)) + l * 4;
    red4(p0, v0 * s0.x, v0 * s0.y, v0 * s0.z, v0 * s0.w);
    if (has1) {
        float* p1 = ((r1 < cl.nA) ? (cl.outA + (size_t)r1 * 64)
                                  : (cl.outB + (size_t)(r1 - cl.nA) * 64)) + l * 4;
        red4(p1, v1 * s1.x, v1 * s1.y, v1 * s1.z, v1 * s1.w);
    }
}

// ---------------- fused relation attention (u and i in one launch) ----------------
__global__ __launch_bounds__(256) void rel_att_both(
    const float* __restrict__ tu, const float* __restrict__ ti,
    const float* __restrict__ t, int U, int I,
    const float* __restrict__ uw1, const float* __restrict__ ub1, const float* __restrict__ uw2,
    const float* __restrict__ iw1, const float* __restrict__ ib1, const float* __restrict__ iw2,
    float* __restrict__ out_u, float* __restrict__ out_i)
{
    __shared__ __align__(16) unsigned long long sW[2][1024];
    __shared__ __align__(16) float zb[8][3][64];
    const int tid = threadIdx.x;
    const int lane = tid & 31;
    const int wid = tid >> 5;

    for (int i = tid; i < 1024; i += 256) {
        int m = i >> 5, h = i & 31;
        sW[0][i] = pk2(uw1[(2 * m) * 32 + h], uw1[(2 * m + 1) * 32 + h]);
        sW[1][i] = pk2(iw1[(2 * m) * 32 + h], iw1[(2 * m + 1) * 32 + h]);
    }
    __syncthreads();

    const int node = blockIdx.x * 8 + wid;
    if (node >= U + I) return;

    const float *z0, *z1, *z2, *b1, *w2;
    float* out;
    const unsigned long long* w;
    int m_;
    if (node < U) {
        m_ = node; z0 = tu; z1 = tu + (size_t)U * 64; z2 = t;
        b1 = ub1; w2 = uw2; out = out_u; w = sW[0];
    } else {
        m_ = node - U; z0 = ti; z1 = ti + (size_t)I * 64; z2 = t + (size_t)U * 64;
        b1 = ib1; w2 = iw2; out = out_i; w = sW[1];
    }
    const float b1v = b1[lane];
    const float w2v = w2[lane];

    size_t base = (size_t)m_ * 64;
    float za0 = z0[base + lane], za1 = z0[base + lane + 32];
    float zc0 = z1[base + lane], zc1 = z1[base + lane + 32];
    float zd0 = z2[base + lane], zd1 = z2[base + lane + 32];
    zb[wid][0][lane] = za0; zb[wid][0][lane + 32] = za1;
    zb[wid][1][lane] = zc0; zb[wid][1][lane + 32] = zc1;
    zb[wid][2][lane] = zd0; zb[wid][2][lane + 32] = zd1;
    __syncwarp();

    float wl[3];
#pragma unroll
    for (int jj = 0; jj < 3; ++jj) {
        const unsigned long long* zp =
            reinterpret_cast<const unsigned long long*>(zb[wid][jj]);
        unsigned long long acc0 = 0ULL, acc1 = 0ULL;   // 2 chains
#pragma unroll
        for (int m = 0; m < 16; ++m) {
            acc0 = fma2(zp[m],      w[m * 32 + lane],        acc0);
            acc1 = fma2(zp[m + 16], w[(m + 16) * 32 + lane], acc1);
        }
        float2 a = up2(acc0);
        float2 bq = up2(acc1);
        float cc = tanhf(a.x + a.y + bq.x + bq.y + b1v) * w2v;
#pragma unroll
        for (int o = 16; o; o >>= 1) cc += __shfl_xor_sync(0xffffffffu, cc, o);
        wl[jj] = cc;
    }
    float mx = fmaxf(wl[0], fmaxf(wl[1], wl[2]));
    float e0 = __expf(wl[0] - mx), e1 = __expf(wl[1] - mx), e2 = __expf(wl[2] - mx);
    float inv = 1.0f / (e0 + e1 + e2);
    float beta0 = e0 * inv, beta1 = e1 * inv, beta2 = e2 * inv;
    out[base + lane]      = beta0 * za0 + beta1 * zc0 + beta2 * zd0;
    out[base + lane + 32] = beta0 * za1 + beta1 * zc1 + beta2 * zd1;
}

// ---------------- host launcher ----------------
extern "C" void kernel_launch(void* const* d_in, const int* in_sizes, int n_in,
                              void* d_out, int out_size)
{
    const int*   u2i_idx  = (const int*)  d_in[0];
    const float* u2i_val  = (const float*)d_in[1];
    const int*   u2e_idx  = (const int*)  d_in[2];
    const float* u2e_val  = (const float*)d_in[3];
    const int*   i2e_idx  = (const int*)  d_in[4];
    const float* i2e_val  = (const float*)d_in[5];
    const float* u_feat   = (const float*)d_in[6];
    const float* i_feat   = (const float*)d_in[7];
    const float* u2e_feat = (const float*)d_in[8];
    const float* i2e_feat = (const float*)d_in[9];
    const float* Tw_u2i = (const float*)d_in[10];
    const float* Tb_u2i = (const float*)d_in[11];
    const float* Iw_u2i = (const float*)d_in[12];
    const float* Ib_u2i = (const float*)d_in[13];
    const float* Tw_u2e = (const float*)d_in[14];
    const float* Tb_u2e = (const float*)d_in[15];
    const float* Iw_u2e = (const float*)d_in[16];
    const float* Ib_u2e = (const float*)d_in[17];
    const float* Tw_i2e = (const float*)d_in[18];
    const float* Tb_i2e = (const float*)d_in[19];
    const float* Iw_i2e = (const float*)d_in[20];
    const float* Ib_i2e = (const float*)d_in[21];
    const float* uatt_w1 = (const float*)d_in[22];
    const float* uatt_b1 = (const float*)d_in[23];
    const float* uatt_w2 = (const float*)d_in[24];
    const float* iatt_w1 = (const float*)d_in[25];
    const float* iatt_b1 = (const float*)d_in[26];
    const float* iatt_w2 = (const float*)d_in[27];

    const int U = in_sizes[6] / 64;
    const int I = in_sizes[7] / 64;
    const int E = in_sizes[8] / (2 * 64);
    const int NNZ_UI = in_sizes[1];
    const int NNZ_E  = in_sizes[3] / 2;

    float *tu, *ti, *t, *s;
    float2 *wT, *wI;
    cudaGetSymbolAddress((void**)&tu, g_tu);
    cudaGetSymbolAddress((void**)&ti, g_ti);
    cudaGetSymbolAddress((void**)&t,  g_t);
    cudaGetSymbolAddress((void**)&s,  g_s);
    cudaGetSymbolAddress((void**)&wT, g_wT);
    cudaGetSymbolAddress((void**)&wI, g_wI);

    float* outp    = (float*)d_out;
    float* out_u   = outp;
    float* out_i   = outp + (size_t)U * 64;
    float* out_u2e = outp + (size_t)(U + I) * 64;
    float* out_i2e = out_u2e + (size_t)2 * E * 64;

    int ns[5]  = {U + E, U + E, I + E, I + E, U + I};
    int rb[6];
    rb[0] = 0;
    for (int i = 0; i < 5; ++i) rb[i + 1] = rb[i] + ns[i];

    // pack weight fragments
    pack_weights<<<40, 256>>>(
        Tw_u2e, Iw_u2e, Tw_u2e + 4096, Iw_u2e + 4096,
        Tw_i2e, Iw_i2e, Tw_i2e + 4096, Iw_i2e + 4096,
        Tw_u2i, Iw_u2i, wT, wI);

    // GEMM table
    GTab gt;
    {
        const float* xAs[5] = {u_feat, u_feat, i_feat, i_feat, u_feat};
        const float* xBs[5] = {u2e_feat, u2e_feat + (size_t)E * 64,
                               i2e_feat, i2e_feat + (size_t)E * 64, i_feat};
        int gnAs[5] = {U, U, I, I, U};
        const float* Tbs[5] = {Tb_u2e, Tb_u2e + 64, Tb_i2e, Tb_i2e + 64, Tb_u2i};
        const float* Ibs[5] = {Ib_u2e, Ib_u2e + 64, Ib_i2e, Ib_i2e + 64, Ib_u2i};
        float* outAs[5] = {tu, tu + (size_t)U * 64, ti, ti + (size_t)I * 64, t};
        float* outBs[5] = {out_u2e, out_u2e + (size_t)E * 64,
                           out_i2e, out_i2e + (size_t)E * 64, t + (size_t)U * 64};
        gt.off[0] = 0;
        for (int i = 0; i < 5; ++i) {
            gt.c[i].xA = xAs[i]; gt.c[i].xB = xBs[i];
            gt.c[i].nA = gnAs[i]; gt.c[i].n = ns[i];
            gt.c[i].wT = wT + (size_t)i * 2048;
            gt.c[i].wI = wI + (size_t)i * 2048;
            gt.c[i].Tb = Tbs[i]; gt.c[i].Ib = Ibs[i];
            gt.c[i].outA = outAs[i]; gt.c[i].outB = outBs[i];
            gt.c[i].s = s + (size_t)rb[i] * 64;
            gt.off[i + 1] = gt.off[i] + (ns[i] + 63) / 64;
        }
    }
    gcn_gemm_all<<<gt.off[5], 128>>>(gt);

    // spmm table
    STab st;
    {
        const int* rws[5] = {u2e_idx, u2e_idx + (size_t)2 * NNZ_E,
                             i2e_idx, i2e_idx + (size_t)2 * NNZ_E, u2i_idx};
        const float* vls[5] = {u2e_val, u2e_val + NNZ_E,
                               i2e_val, i2e_val + NNZ_E, u2i_val};
        int nnzs[5] = {NNZ_E, NNZ_E, NNZ_E, NNZ_E, NNZ_UI};
        int nAs[5]  = {U, U, I, I, U + I};
        float* outAs[5] = {tu, tu + (size_t)U * 64, ti, ti + (size_t)I * 64, t};
        float* outBs[5] = {out_u2e, out_u2e + (size_t)E * 64,
                           out_i2e, out_i2e + (size_t)E * 64, t};
        st.off[0] = 0;
        for (int i = 0; i < 5; ++i) {
            st.c[i].rows = rws[i];
            st.c[i].cols = rws[i] + nnzs[i];
            st.c[i].vals = vls[i];
            st.c[i].nnz = nnzs[i];
            st.c[i].sIn = s + (size_t)rb[i] * 64;
            st.c[i].outA = outAs[i];
            st.c[i].nA = nAs[i];
            st.c[i].outB = outBs[i];
            long long th = ((long long)nnzs[i] + 1) / 2 * 16;
            st.off[i + 1] = st.off[i] + (int)((th + 255) / 256);
        }
    }
    spmm_all<<<st.off[5], 256>>>(st);

    // fused attention
    rel_att_both<<<(U + I + 7) / 8, 256>>>(
        tu, ti, t, U, I,
        uatt_w1, uatt_b1, uatt_w2,
        iatt_w1, iatt_b1, iatt_w2,
        out_u, out_i);
}

// round 6
// speedup vs baseline: 1.4646x; 1.1463x over previous
#include <cuda_runtime.h>
#include <cstdint>
#include <cstdio>

// ---------------- scratch (static device globals; no allocation) ----------------
__device__ float g_tu[2 * 100000 * 64];
__device__ float g_ti[2 * 100000 * 64];
__device__ float g_t [200000 * 64];
__device__ float g_s [800000 * 64];          // per-cell s buffers, cumulative rows
__device__ float2 g_wT[5 * 2048];            // packed tf32 T-weight frags
__device__ float2 g_wI[5 * 2048];            // packed tf32 I-weight frags
__device__ float2 g_awf[2048];               // packed tf32 attention w1 frags (u,i)

// ---------------- helpers ----------------
__device__ __forceinline__ void red4(float* p, float a, float b, float c, float d) {
    asm volatile("red.global.add.v4.f32 [%0], {%1, %2, %3, %4};"
                 :: "l"(p), "f"(a), "f"(b), "f"(c), "f"(d) : "memory");
}
__device__ __forceinline__ unsigned int tf32c(float f) {
    unsigned int r;
    asm("cvt.rna.tf32.f32 %0, %1;" : "=r"(r) : "f"(f));
    return r;
}
__device__ __forceinline__ void mma_tf32(float c[4],
                                         unsigned int a0, unsigned int a1,
                                         unsigned int a2, unsigned int a3,
                                         unsigned int b0, unsigned int b1) {
    asm("mma.sync.aligned.m16n8k8.row.col.f32.tf32.tf32.f32 "
        "{%0,%1,%2,%3}, {%4,%5,%6,%7}, {%8,%9}, {%0,%1,%2,%3};"
        : "+f"(c[0]), "+f"(c[1]), "+f"(c[2]), "+f"(c[3])
        : "r"(a0), "r"(a1), "r"(a2), "r"(a3), "r"(b0), "r"(b1));
}

// ---------------- descriptor tables ----------------
struct GCell {
    const float* xA; const float* xB; int nA; int n;
    const float2* wT; const float2* wI;
    const float* Tb; const float* Ib;
    float* outA; float* outB; float* s;
};
struct GTab { int off[6]; GCell c[5]; };

struct SCell {
    const int* rows; const int* cols; const float* vals; int nnz;
    const float* sIn; float* outA; int nA; float* outB;
};
struct STab { int off[6]; SCell c[5]; };

// ---------------- weight fragment packers ----------------
__global__ __launch_bounds__(256) void pack_weights(
    const float* tw0, const float* iw0, const float* tw1, const float* iw1,
    const float* tw2, const float* iw2, const float* tw3, const float* iw3,
    const float* tw4, const float* iw4, float2* wT, float2* wI)
{
    int idx = blockIdx.x * 256 + threadIdx.x;
    if (idx >= 5 * 2048) return;
    int c = idx >> 11;
    int kt = (idx >> 8) & 7;
    int nt = (idx >> 5) & 7;
    int l = idx & 31;
    const float* tw; const float* iw;
    switch (c) {
        case 0: tw = tw0; iw = iw0; break;
        case 1: tw = tw1; iw = iw1; break;
        case 2: tw = tw2; iw = iw2; break;
        case 3: tw = tw3; iw = iw3; break;
        default: tw = tw4; iw = iw4; break;
    }
    int k0 = kt * 8 + (l & 3);
    int n0 = nt * 8 + (l >> 2);
    float2 ot, oi;
    ot.x = __uint_as_float(tf32c(tw[k0 * 64 + n0]));
    ot.y = __uint_as_float(tf32c(tw[(k0 + 4) * 64 + n0]));
    oi.x = __uint_as_float(tf32c(iw[k0 * 64 + n0]));
    oi.y = __uint_as_float(tf32c(iw[(k0 + 4) * 64 + n0]));
    wT[idx] = ot;
    wI[idx] = oi;
}

// attention w1 (64x32) -> B-fragments: [set(2)][kt(8)][nt(4)][lane(32)]
__global__ __launch_bounds__(256) void pack_att(
    const float* uw1, const float* iw1, float2* awf)
{
    int idx = blockIdx.x * 256 + threadIdx.x;
    if (idx >= 2048) return;
    int set = idx >> 10;
    int kt = (idx >> 7) & 7;
    int nt = (idx >> 5) & 3;
    int l = idx & 31;
    const float* w = set ? iw1 : uw1;
    int k0 = kt * 8 + (l & 3);
    int n0 = nt * 8 + (l >> 2);
    awf[idx] = make_float2(
        __uint_as_float(tf32c(w[k0 * 32 + n0])),
        __uint_as_float(tf32c(w[(k0 + 4) * 32 + n0])));
}

// ---------------- fused dual GEMM (all 5 cells, one launch) ----------------
__global__ __launch_bounds__(128, 5) void gcn_gemm_all(GTab tab)
{
    __shared__ __align__(16) float sX[64 * 68];
    int b = blockIdx.x;
    int c = 0;
#pragma unroll
    for (int i = 1; i < 5; ++i) c += (b >= tab.off[i]);
    const GCell cl = tab.c[c];
    const int row0 = (b - tab.off[c]) * 64;
    const int tid = threadIdx.x;
    const int n = cl.n;

    for (int i = tid; i < 64 * 16; i += 128) {
        int r = i >> 4, c4 = i & 15;
        int gr = row0 + r;
        float4 v = make_float4(0.f, 0.f, 0.f, 0.f);
        if (gr < n) {
            const float* src = (gr < cl.nA) ? (cl.xA + (size_t)gr * 64)
                                            : (cl.xB + (size_t)(gr - cl.nA) * 64);
            v = *reinterpret_cast<const float4*>(src + c4 * 4);
        }
        *reinterpret_cast<float4*>(sX + r * 68 + c4 * 4) = v;
    }
    __syncthreads();

    const int wid = tid >> 5;
    const int lane = tid & 31;
    const int g = lane >> 2;
    const int t4 = lane & 3;
    const float* xr0 = sX + (wid * 16 + g) * 68;
    const float* xr1 = xr0 + 8 * 68;

    float xf0[8], xf1[8], xf2[8], xf3[8];
#pragma unroll
    for (int kt = 0; kt < 8; ++kt) {
        int c0 = kt * 8 + t4;
        xf0[kt] = xr0[c0];
        xf1[kt] = xr1[c0];
        xf2[kt] = xr0[c0 + 4];
        xf3[kt] = xr1[c0 + 4];
    }

    float acc[8][4];
#pragma unroll
    for (int nt = 0; nt < 8; ++nt)
#pragma unroll
        for (int i = 0; i < 4; ++i) acc[nt][i] = 0.f;

    // T phase
#pragma unroll
    for (int kt = 0; kt < 8; ++kt) {
        unsigned int a0 = tf32c(xf0[kt]), a1 = tf32c(xf1[kt]);
        unsigned int a2 = tf32c(xf2[kt]), a3 = tf32c(xf3[kt]);
        const float2* wr = cl.wT + kt * 256 + lane;
#pragma unroll
        for (int nt = 0; nt < 8; ++nt) {
            float2 w = wr[nt * 32];
            mma_tf32(acc[nt], a0, a1, a2, a3,
                     __float_as_uint(w.x), __float_as_uint(w.y));
        }
    }

    const int r0 = row0 + wid * 16 + g;
    const int r1 = r0 + 8;
    float* op0 = nullptr; float* op1 = nullptr;
    if (r0 < n) op0 = (r0 < cl.nA) ? (cl.outA + (size_t)r0 * 64)
                                   : (cl.outB + (size_t)(r0 - cl.nA) * 64);
    if (r1 < n) op1 = (r1 < cl.nA) ? (cl.outA + (size_t)r1 * 64)
                                   : (cl.outB + (size_t)(r1 - cl.nA) * 64);

    // midpoint epilogue: write t = acc + Tb
#pragma unroll
    for (int nt = 0; nt < 8; ++nt) {
        int col = nt * 8 + 2 * t4;
        float tbx = cl.Tb[col], tby = cl.Tb[col + 1];
        if (op0) *reinterpret_cast<float2*>(op0 + col) =
            make_float2(acc[nt][0] + tbx, acc[nt][1] + tby);
        if (op1) *reinterpret_cast<float2*>(op1 + col) =
            make_float2(acc[nt][2] + tbx, acc[nt][3] + tby);
    }

    // Q phase (accumulates on top of T)
#pragma unroll
    for (int kt = 0; kt < 8; ++kt) {
        unsigned int q0 = tf32c(xf0[kt] * xf0[kt]), q1 = tf32c(xf1[kt] * xf1[kt]);
        unsigned int q2 = tf32c(xf2[kt] * xf2[kt]), q3 = tf32c(xf3[kt] * xf3[kt]);
        const float2* wr = cl.wI + kt * 256 + lane;
#pragma unroll
        for (int nt = 0; nt < 8; ++nt) {
            float2 w = wr[nt * 32];
            mma_tf32(acc[nt], q0, q1, q2, q3,
                     __float_as_uint(w.x), __float_as_uint(w.y));
        }
    }

    // final epilogue: write s = acc + Tb + Ib
#pragma unroll
    for (int nt = 0; nt < 8; ++nt) {
        int col = nt * 8 + 2 * t4;
        float sbx = cl.Tb[col] + cl.Ib[col];
        float sby = cl.Tb[col + 1] + cl.Ib[col + 1];
        if (r0 < n) *reinterpret_cast<float2*>(cl.s + (size_t)r0 * 64 + col) =
            make_float2(acc[nt][0] + sbx, acc[nt][1] + sby);
        if (r1 < n) *reinterpret_cast<float2*>(cl.s + (size_t)r1 * 64 + col) =
            make_float2(acc[nt][2] + sbx, acc[nt][3] + sby);
    }
}

// ---------------- fused edge scatter (all 5 cells, one launch) ----------------
__global__ __launch_bounds__(256) void spmm_all(STab tab)
{
    int b = blockIdx.x;
    int c = 0;
#pragma unroll
    for (int i = 1; i < 5; ++i) c += (b >= tab.off[i]);
    const SCell cl = tab.c[c];
    long long t = (long long)(b - tab.off[c]) * 256 + threadIdx.x;
    int l = (int)(t & 15);
    int e0 = (int)(t >> 4) * 2;
    if (e0 >= cl.nnz) return;

    int r0 = __ldg(cl.rows + e0);
    int c0 = __ldg(cl.cols + e0);
    float v0 = __ldg(cl.vals + e0);
    bool has1 = (e0 + 1) < cl.nnz;
    int r1 = r0, c1 = c0;
    float v1 = 0.f;
    if (has1) {
        r1 = __ldg(cl.rows + e0 + 1);
        c1 = __ldg(cl.cols + e0 + 1);
        v1 = __ldg(cl.vals + e0 + 1);
    }
    float4 s0 = *reinterpret_cast<const float4*>(cl.sIn + (size_t)c0 * 64 + l * 4);
    float4 s1 = *reinterpret_cast<const float4*>(cl.sIn + (size_t)c1 * 64 + l * 4);

    float* p0 = ((r0 < cl.nA) ? (cl.outA + (size_t)r0 * 64)
                              : (cl.outB + (size_t)(r0 - cl.nA) * 64)) + l * 4;
    red4(p0, v0 * s0.x, v0 * s0.y, v0 * s0.z, v0 * s0.w);
    if (has1) {
        float* p1 = ((r1 < cl.nA) ? (cl.outA + (size_t)r1 * 64)
                                  : (cl.outB + (size_t)(r1 - cl.nA) * 64)) + l * 4;
        red4(p1, v1 * s1.x, v1 * s1.y, v1 * s1.z, v1 * s1.w);
    }
}

// ---------------- tensor-core relation attention ----------------
// Block = 128 thr, 64 nodes. Stage 3 z-tiles in smem; scores via tf32 MMA;
// softmax + combine from the same smem tiles. z reads DRAM exactly once.
#define ATT_TILE_F (64 * 68)
#define ATT_SMEM_F (3 * ATT_TILE_F + 256)

__global__ __launch_bounds__(128) void rel_att_tc(
    const float* __restrict__ tu, const float* __restrict__ ti,
    const float* __restrict__ t, int U, int I, int nbU,
    const float2* __restrict__ awf,
    const float* __restrict__ ub1, const float* __restrict__ uw2,
    const float* __restrict__ ib1, const float* __restrict__ iw2,
    float* __restrict__ out_u, float* __restrict__ out_i)
{
    extern __shared__ __align__(16) float sm[];
    const int b = blockIdx.x;
    const bool isU = b < nbU;
    const int node0 = (isU ? b : (b - nbU)) * 64;
    const int N = isU ? U : I;
    const float* zB[3];
    if (isU) { zB[0] = tu; zB[1] = tu + (size_t)U * 64; zB[2] = t; }
    else     { zB[0] = ti; zB[1] = ti + (size_t)I * 64; zB[2] = t + (size_t)U * 64; }
    const float* b1 = isU ? ub1 : ib1;
    const float* w2 = isU ? uw2 : iw2;
    const float2* wf = awf + (isU ? 0 : 1024);
    float* out = isU ? out_u : out_i;

    const int tid = threadIdx.x;

    // stage 3 z tiles (64 rows x 64 floats each, pad stride 68)
#pragma unroll
    for (int r = 0; r < 3; ++r) {
        const float* zr = zB[r];
        float* dst = sm + r * ATT_TILE_F;
        for (int i = tid; i < 64 * 16; i += 128) {
            int row = i >> 4, c4 = i & 15;
            int gr = node0 + row;
            float4 v = make_float4(0.f, 0.f, 0.f, 0.f);
            if (gr < N) v = *reinterpret_cast<const float4*>(zr + (size_t)gr * 64 + c4 * 4);
            *reinterpret_cast<float4*>(dst + row * 68 + c4 * 4) = v;
        }
    }
    __syncthreads();

    const int wid = tid >> 5;
    const int lane = tid & 31;
    const int g = lane >> 2;
    const int t4 = lane & 3;
    float* wl = sm + 3 * ATT_TILE_F;   // wl[row*4 + rel]

    // scores: wl = tanh(z @ w1 + b1) @ w2 per relation
#pragma unroll
    for (int rel = 0; rel < 3; ++rel) {
        const float* xr0 = sm + rel * ATT_TILE_F + (wid * 16 + g) * 68;
        const float* xr1 = xr0 + 8 * 68;
        float acc[4][4];
#pragma unroll
        for (int nt = 0; nt < 4; ++nt)
#pragma unroll
            for (int i = 0; i < 4; ++i) acc[nt][i] = 0.f;
#pragma unroll
        for (int kt = 0; kt < 8; ++kt) {
            int c0 = kt * 8 + t4;
            unsigned int a0 = tf32c(xr0[c0]);
            unsigned int a1 = tf32c(xr1[c0]);
            unsigned int a2 = tf32c(xr0[c0 + 4]);
            unsigned int a3 = tf32c(xr1[c0 + 4]);
            const float2* wr = wf + kt * 128 + lane;
#pragma unroll
            for (int nt = 0; nt < 4; ++nt) {
                float2 w = wr[nt * 32];
                mma_tf32(acc[nt], a0, a1, a2, a3,
                         __float_as_uint(w.x), __float_as_uint(w.y));
            }
        }
        // epilogue: tanh, *w2, row-sum over 32 cols
        float s0 = 0.f, s1 = 0.f;
#pragma unroll
        for (int nt = 0; nt < 4; ++nt) {
            int col = nt * 8 + 2 * t4;
            float b1x = b1[col], b1y = b1[col + 1];
            float w2x = w2[col], w2y = w2[col + 1];
            s0 += tanhf(acc[nt][0] + b1x) * w2x + tanhf(acc[nt][1] + b1y) * w2y;
            s1 += tanhf(acc[nt][2] + b1x) * w2x + tanhf(acc[nt][3] + b1y) * w2y;
        }
        s0 += __shfl_xor_sync(0xffffffffu, s0, 1);
        s0 += __shfl_xor_sync(0xffffffffu, s0, 2);
        s1 += __shfl_xor_sync(0xffffffffu, s1, 1);
        s1 += __shfl_xor_sync(0xffffffffu, s1, 2);
        if (t4 == 0) {
            int r0 = wid * 16 + g;
            wl[r0 * 4 + rel] = s0;
            wl[(r0 + 8) * 4 + rel] = s1;
        }
    }
    __syncthreads();

    // combine: thread -> (row = tid>>1, half = tid&1)
    {
        int row = tid >> 1;
        int gr = node0 + row;
        if (gr < N) {
            float w0 = wl[row * 4 + 0], w1v = wl[row * 4 + 1], w2v = wl[row * 4 + 2];
            float mx = fmaxf(w0, fmaxf(w1v, w2v));
            float e0 = __expf(w0 - mx), e1 = __expf(w1v - mx), e2 = __expf(w2v - mx);
            float inv = 1.0f / (e0 + e1 + e2);
            float beta0 = e0 * inv, beta1 = e1 * inv, beta2 = e2 * inv;
            int hoff = (tid & 1) * 32;
            const float* z0p = sm + 0 * ATT_TILE_F + row * 68 + hoff;
            const float* z1p = sm + 1 * ATT_TILE_F + row * 68 + hoff;
            const float* z2p = sm + 2 * ATT_TILE_F + row * 68 + hoff;
            float* op = out + (size_t)gr * 64 + hoff;
#pragma unroll
            for (int i = 0; i < 8; ++i) {
                float4 A = *reinterpret_cast<const float4*>(z0p + i * 4);
                float4 B = *reinterpret_cast<const float4*>(z1p + i * 4);
                float4 C = *reinterpret_cast<const float4*>(z2p + i * 4);
                float4 o;
                o.x = beta0 * A.x + beta1 * B.x + beta2 * C.x;
                o.y = beta0 * A.y + beta1 * B.y + beta2 * C.y;
                o.z = beta0 * A.z + beta1 * B.z + beta2 * C.z;
                o.w = beta0 * A.w + beta1 * B.w + beta2 * C.w;
                *reinterpret_cast<float4*>(op + i * 4) = o;
            }
        }
    }
}

// ---------------- host launcher ----------------
extern "C" void kernel_launch(void* const* d_in, const int* in_sizes, int n_in,
                              void* d_out, int out_size)
{
    const int*   u2i_idx  = (const int*)  d_in[0];
    const float* u2i_val  = (const float*)d_in[1];
    const int*   u2e_idx  = (const int*)  d_in[2];
    const float* u2e_val  = (const float*)d_in[3];
    const int*   i2e_idx  = (const int*)  d_in[4];
    const float* i2e_val  = (const float*)d_in[5];
    const float* u_feat   = (const float*)d_in[6];
    const float* i_feat   = (const float*)d_in[7];
    const float* u2e_feat = (const float*)d_in[8];
    const float* i2e_feat = (const float*)d_in[9];
    const float* Tw_u2i = (const float*)d_in[10];
    const float* Tb_u2i = (const float*)d_in[11];
    const float* Iw_u2i = (const float*)d_in[12];
    const float* Ib_u2i = (const float*)d_in[13];
    const float* Tw_u2e = (const float*)d_in[14];
    const float* Tb_u2e = (const float*)d_in[15];
    const float* Iw_u2e = (const float*)d_in[16];
    const float* Ib_u2e = (const float*)d_in[17];
    const float* Tw_i2e = (const float*)d_in[18];
    const float* Tb_i2e = (const float*)d_in[19];
    const float* Iw_i2e = (const float*)d_in[20];
    const float* Ib_i2e = (const float*)d_in[21];
    const float* uatt_w1 = (const float*)d_in[22];
    const float* uatt_b1 = (const float*)d_in[23];
    const float* uatt_w2 = (const float*)d_in[24];
    const float* iatt_w1 = (const float*)d_in[25];
    const float* iatt_b1 = (const float*)d_in[26];
    const float* iatt_w2 = (const float*)d_in[27];

    const int U = in_sizes[6] / 64;
    const int I = in_sizes[7] / 64;
    const int E = in_sizes[8] / (2 * 64);
    const int NNZ_UI = in_sizes[1];
    const int NNZ_E  = in_sizes[3] / 2;

    float *tu, *ti, *t, *s;
    float2 *wT, *wI, *awf;
    cudaGetSymbolAddress((void**)&tu, g_tu);
    cudaGetSymbolAddress((void**)&ti, g_ti);
    cudaGetSymbolAddress((void**)&t,  g_t);
    cudaGetSymbolAddress((void**)&s,  g_s);
    cudaGetSymbolAddress((void**)&wT, g_wT);
    cudaGetSymbolAddress((void**)&wI, g_wI);
    cudaGetSymbolAddress((void**)&awf, g_awf);

    float* outp    = (float*)d_out;
    float* out_u   = outp;
    float* out_i   = outp + (size_t)U * 64;
    float* out_u2e = outp + (size_t)(U + I) * 64;
    float* out_i2e = out_u2e + (size_t)2 * E * 64;

    int ns[5]  = {U + E, U + E, I + E, I + E, U + I};
    int rb[6];
    rb[0] = 0;
    for (int i = 0; i < 5; ++i) rb[i + 1] = rb[i] + ns[i];

    // pack weight fragments
    pack_weights<<<40, 256>>>(
        Tw_u2e, Iw_u2e, Tw_u2e + 4096, Iw_u2e + 4096,
        Tw_i2e, Iw_i2e, Tw_i2e + 4096, Iw_i2e + 4096,
        Tw_u2i, Iw_u2i, wT, wI);
    pack_att<<<8, 256>>>(uatt_w1, iatt_w1, awf);

    // GEMM table
    GTab gt;
    {
        const float* xAs[5] = {u_feat, u_feat, i_feat, i_feat, u_feat};
        const float* xBs[5] = {u2e_feat, u2e_feat + (size_t)E * 64,
                               i2e_feat, i2e_feat + (size_t)E * 64, i_feat};
        int gnAs[5] = {U, U, I, I, U};
        const float* Tbs[5] = {Tb_u2e, Tb_u2e + 64, Tb_i2e, Tb_i2e + 64, Tb_u2i};
        const float* Ibs[5] = {Ib_u2e, Ib_u2e + 64, Ib_i2e, Ib_i2e + 64, Ib_u2i};
        float* outAs[5] = {tu, tu + (size_t)U * 64, ti, ti + (size_t)I * 64, t};
        float* outBs[5] = {out_u2e, out_u2e + (size_t)E * 64,
                           out_i2e, out_i2e + (size_t)E * 64, t + (size_t)U * 64};
        gt.off[0] = 0;
        for (int i = 0; i < 5; ++i) {
            gt.c[i].xA = xAs[i]; gt.c[i].xB = xBs[i];
            gt.c[i].nA = gnAs[i]; gt.c[i].n = ns[i];
            gt.c[i].wT = wT + (size_t)i * 2048;
            gt.c[i].wI = wI + (size_t)i * 2048;
            gt.c[i].Tb = Tbs[i]; gt.c[i].Ib = Ibs[i];
            gt.c[i].outA = outAs[i]; gt.c[i].outB = outBs[i];
            gt.c[i].s = s + (size_t)rb[i] * 64;
            gt.off[i + 1] = gt.off[i] + (ns[i] + 63) / 64;
        }
    }
    gcn_gemm_all<<<gt.off[5], 128>>>(gt);

    // spmm table
    STab st;
    {
        const int* rws[5] = {u2e_idx, u2e_idx + (size_t)2 * NNZ_E,
                             i2e_idx, i2e_idx + (size_t)2 * NNZ_E, u2i_idx};
        const float* vls[5] = {u2e_val, u2e_val + NNZ_E,
                               i2e_val, i2e_val + NNZ_E, u2i_val};
        int nnzs[5] = {NNZ_E, NNZ_E, NNZ_E, NNZ_E, NNZ_UI};
        int nAs[5]  = {U, U, I, I, U + I};
        float* outAs[5] = {tu, tu + (size_t)U * 64, ti, ti + (size_t)I * 64, t};
        float* outBs[5] = {out_u2e, out_u2e + (size_t)E * 64,
                           out_i2e, out_i2e + (size_t)E * 64, t};
        st.off[0] = 0;
        for (int i = 0; i < 5; ++i) {
            st.c[i].rows = rws[i];
            st.c[i].cols = rws[i] + nnzs[i];
            st.c[i].vals = vls[i];
            st.c[i].nnz = nnzs[i];
            st.c[i].sIn = s + (size_t)rb[i] * 64;
            st.c[i].outA = outAs[i];
            st.c[i].nA = nAs[i];
            st.c[i].outB = outBs[i];
            long long th = ((long long)nnzs[i] + 1) / 2 * 16;
            st.off[i + 1] = st.off[i] + (int)((th + 255) / 256);
        }
    }
    spmm_all<<<st.off[5], 256>>>(st);

    // tensor-core attention (52KB dynamic smem)
    const int smemB = ATT_SMEM_F * 4;
    cudaFuncSetAttribute(rel_att_tc, cudaFuncAttributeMaxDynamicSharedMemorySize, smemB);
    int nbU = (U + 63) / 64, nbI = (I + 63) / 64;
    rel_att_tc<<<nbU + nbI, 128, smemB>>>(
        tu, ti, t, U, I, nbU, awf,
        uatt_b1, uatt_w2, iatt_b1, iatt_w2,
        out_u, out_i);
}

// round 7
// speedup vs baseline: 1.4655x; 1.0006x over previous
#include <cuda_runtime.h>
#include <cstdint>
#include <cstdio>

// ---------------- scratch (static device globals; no allocation) ----------------
__device__ float g_tu[2 * 100000 * 64];
__device__ float g_ti[2 * 100000 * 64];
__device__ float g_t [200000 * 64];
__device__ float g_s [800000 * 64];          // per-cell s buffers, cumulative rows
__device__ float2 g_wT[5 * 2048];            // packed tf32 T-weight frags
__device__ float2 g_wI[5 * 2048];            // packed tf32 I-weight frags
__device__ float2 g_awf[2048];               // packed tf32 attention w1 frags (u,i)

// ---------------- helpers ----------------
__device__ __forceinline__ void red4(float* p, float a, float b, float c, float d) {
    asm volatile("red.global.add.v4.f32 [%0], {%1, %2, %3, %4};"
                 :: "l"(p), "f"(a), "f"(b), "f"(c), "f"(d) : "memory");
}
__device__ __forceinline__ unsigned int tf32c(float f) {
    unsigned int r;
    asm("cvt.rna.tf32.f32 %0, %1;" : "=r"(r) : "f"(f));
    return r;
}
__device__ __forceinline__ void mma_tf32(float c[4],
                                         unsigned int a0, unsigned int a1,
                                         unsigned int a2, unsigned int a3,
                                         unsigned int b0, unsigned int b1) {
    asm("mma.sync.aligned.m16n8k8.row.col.f32.tf32.tf32.f32 "
        "{%0,%1,%2,%3}, {%4,%5,%6,%7}, {%8,%9}, {%0,%1,%2,%3};"
        : "+f"(c[0]), "+f"(c[1]), "+f"(c[2]), "+f"(c[3])
        : "r"(a0), "r"(a1), "r"(a2), "r"(a3), "r"(b0), "r"(b1));
}

// ---------------- descriptor tables ----------------
struct GCell {
    const float* xA; const float* xB; int nA; int n;
    const float2* wT; const float2* wI;
    const float* Tb; const float* Ib;
    float* outA; float* outB; float* s;
};
struct GTab { int off[6]; GCell c[5]; };

struct SCell {
    const int* rows; const int* cols; const float* vals; int nnz;
    const float* sIn; float* outA; int nA; float* outB;
};
struct STab { int off[6]; SCell c[5]; };

// ---------------- weight fragment packers ----------------
__global__ __launch_bounds__(256) void pack_weights(
    const float* tw0, const float* iw0, const float* tw1, const float* iw1,
    const float* tw2, const float* iw2, const float* tw3, const float* iw3,
    const float* tw4, const float* iw4, float2* wT, float2* wI)
{
    int idx = blockIdx.x * 256 + threadIdx.x;
    if (idx >= 5 * 2048) return;
    int c = idx >> 11;
    int kt = (idx >> 8) & 7;
    int nt = (idx >> 5) & 7;
    int l = idx & 31;
    const float* tw; const float* iw;
    switch (c) {
        case 0: tw = tw0; iw = iw0; break;
        case 1: tw = tw1; iw = iw1; break;
        case 2: tw = tw2; iw = iw2; break;
        case 3: tw = tw3; iw = iw3; break;
        default: tw = tw4; iw = iw4; break;
    }
    int k0 = kt * 8 + (l & 3);
    int n0 = nt * 8 + (l >> 2);
    float2 ot, oi;
    ot.x = __uint_as_float(tf32c(tw[k0 * 64 + n0]));
    ot.y = __uint_as_float(tf32c(tw[(k0 + 4) * 64 + n0]));
    oi.x = __uint_as_float(tf32c(iw[k0 * 64 + n0]));
    oi.y = __uint_as_float(tf32c(iw[(k0 + 4) * 64 + n0]));
    wT[idx] = ot;
    wI[idx] = oi;
}

// attention w1 (64x32) -> B-fragments: [set(2)][kt(8)][nt(4)][lane(32)]
__global__ __launch_bounds__(256) void pack_att(
    const float* uw1, const float* iw1, float2* awf)
{
    int idx = blockIdx.x * 256 + threadIdx.x;
    if (idx >= 2048) return;
    int set = idx >> 10;
    int kt = (idx >> 7) & 7;
    int nt = (idx >> 5) & 3;
    int l = idx & 31;
    const float* w = set ? iw1 : uw1;
    int k0 = kt * 8 + (l & 3);
    int n0 = nt * 8 + (l >> 2);
    awf[idx] = make_float2(
        __uint_as_float(tf32c(w[k0 * 32 + n0])),
        __uint_as_float(tf32c(w[(k0 + 4) * 32 + n0])));
}

// ---------------- fused dual GEMM (all 5 cells, one launch) ----------------
// x fragments re-read from smem each phase (no persistent x regs) -> higher occ.
__global__ __launch_bounds__(128, 6) void gcn_gemm_all(GTab tab)
{
    __shared__ __align__(16) float sX[64 * 68];
    int b = blockIdx.x;
    int c = 0;
#pragma unroll
    for (int i = 1; i < 5; ++i) c += (b >= tab.off[i]);
    const GCell cl = tab.c[c];
    const int row0 = (b - tab.off[c]) * 64;
    const int tid = threadIdx.x;
    const int n = cl.n;

    for (int i = tid; i < 64 * 16; i += 128) {
        int r = i >> 4, c4 = i & 15;
        int gr = row0 + r;
        float4 v = make_float4(0.f, 0.f, 0.f, 0.f);
        if (gr < n) {
            const float* src = (gr < cl.nA) ? (cl.xA + (size_t)gr * 64)
                                            : (cl.xB + (size_t)(gr - cl.nA) * 64);
            v = *reinterpret_cast<const float4*>(src + c4 * 4);
        }
        *reinterpret_cast<float4*>(sX + r * 68 + c4 * 4) = v;
    }
    __syncthreads();

    const int wid = tid >> 5;
    const int lane = tid & 31;
    const int g = lane >> 2;
    const int t4 = lane & 3;
    const float* xr0 = sX + (wid * 16 + g) * 68;
    const float* xr1 = xr0 + 8 * 68;

    float acc[8][4];
#pragma unroll
    for (int nt = 0; nt < 8; ++nt)
#pragma unroll
        for (int i = 0; i < 4; ++i) acc[nt][i] = 0.f;

    // T phase
#pragma unroll
    for (int kt = 0; kt < 8; ++kt) {
        int c0 = kt * 8 + t4;
        unsigned int a0 = tf32c(xr0[c0]);
        unsigned int a1 = tf32c(xr1[c0]);
        unsigned int a2 = tf32c(xr0[c0 + 4]);
        unsigned int a3 = tf32c(xr1[c0 + 4]);
        const float2* wr = cl.wT + kt * 256 + lane;
#pragma unroll
        for (int nt = 0; nt < 8; ++nt) {
            float2 w = wr[nt * 32];
            mma_tf32(acc[nt], a0, a1, a2, a3,
                     __float_as_uint(w.x), __float_as_uint(w.y));
        }
    }

    const int r0 = row0 + wid * 16 + g;
    const int r1 = r0 + 8;
    float* op0 = nullptr; float* op1 = nullptr;
    if (r0 < n) op0 = (r0 < cl.nA) ? (cl.outA + (size_t)r0 * 64)
                                   : (cl.outB + (size_t)(r0 - cl.nA) * 64);
    if (r1 < n) op1 = (r1 < cl.nA) ? (cl.outA + (size_t)r1 * 64)
                                   : (cl.outB + (size_t)(r1 - cl.nA) * 64);

    // midpoint epilogue: write t = acc + Tb
#pragma unroll
    for (int nt = 0; nt < 8; ++nt) {
        int col = nt * 8 + 2 * t4;
        float tbx = cl.Tb[col], tby = cl.Tb[col + 1];
        if (op0) *reinterpret_cast<float2*>(op0 + col) =
            make_float2(acc[nt][0] + tbx, acc[nt][1] + tby);
        if (op1) *reinterpret_cast<float2*>(op1 + col) =
            make_float2(acc[nt][2] + tbx, acc[nt][3] + tby);
    }

    // Q phase (accumulates on top of T); x re-read from smem, squared
#pragma unroll
    for (int kt = 0; kt < 8; ++kt) {
        int c0 = kt * 8 + t4;
        float x0 = xr0[c0], x1 = xr1[c0], x2 = xr0[c0 + 4], x3 = xr1[c0 + 4];
        unsigned int q0 = tf32c(x0 * x0);
        unsigned int q1 = tf32c(x1 * x1);
        unsigned int q2 = tf32c(x2 * x2);
        unsigned int q3 = tf32c(x3 * x3);
        const float2* wr = cl.wI + kt * 256 + lane;
#pragma unroll
        for (int nt = 0; nt < 8; ++nt) {
            float2 w = wr[nt * 32];
            mma_tf32(acc[nt], q0, q1, q2, q3,
                     __float_as_uint(w.x), __float_as_uint(w.y));
        }
    }

    // final epilogue: write s = acc + Tb + Ib
#pragma unroll
    for (int nt = 0; nt < 8; ++nt) {
        int col = nt * 8 + 2 * t4;
        float sbx = cl.Tb[col] + cl.Ib[col];
        float sby = cl.Tb[col + 1] + cl.Ib[col + 1];
        if (r0 < n) *reinterpret_cast<float2*>(cl.s + (size_t)r0 * 64 + col) =
            make_float2(acc[nt][0] + sbx, acc[nt][1] + sby);
        if (r1 < n) *reinterpret_cast<float2*>(cl.s + (size_t)r1 * 64 + col) =
            make_float2(acc[nt][2] + sbx, acc[nt][3] + sby);
    }
}

// ---------------- fused edge scatter (all 5 cells, one launch) ----------------
// 16 lanes per edge, 4 edges per thread (MLP=4), coalesced gathers + red.v4.
__global__ __launch_bounds__(256) void spmm_all(STab tab)
{
    int b = blockIdx.x;
    int c = 0;
#pragma unroll
    for (int i = 1; i < 5; ++i) c += (b >= tab.off[i]);
    const SCell cl = tab.c[c];
    long long t = (long long)(b - tab.off[c]) * 256 + threadIdx.x;
    int l = (int)(t & 15);
    int e0 = (int)(t >> 4) * 4;
    if (e0 >= cl.nnz) return;

    int rr[4], cc[4];
    float vv[4];
#pragma unroll
    for (int j = 0; j < 4; ++j) {
        int e = min(e0 + j, cl.nnz - 1);
        rr[j] = __ldg(cl.rows + e);
        cc[j] = __ldg(cl.cols + e);
        vv[j] = (e0 + j < cl.nnz) ? __ldg(cl.vals + e) : 0.f;
    }
    // all gathers in flight before any red -> MLP 4
    float4 sv[4];
#pragma unroll
    for (int j = 0; j < 4; ++j)
        sv[j] = *reinterpret_cast<const float4*>(cl.sIn + (size_t)cc[j] * 64 + l * 4);

#pragma unroll
    for (int j = 0; j < 4; ++j) {
        if (e0 + j < cl.nnz) {
            float* p = ((rr[j] < cl.nA) ? (cl.outA + (size_t)rr[j] * 64)
                                        : (cl.outB + (size_t)(rr[j] - cl.nA) * 64)) + l * 4;
            red4(p, vv[j] * sv[j].x, vv[j] * sv[j].y, vv[j] * sv[j].z, vv[j] * sv[j].w);
        }
    }
}

// ---------------- tensor-core relation attention ----------------
#define ATT_TILE_F (64 * 68)
#define ATT_SMEM_F (3 * ATT_TILE_F + 256)

__global__ __launch_bounds__(128) void rel_att_tc(
    const float* __restrict__ tu, const float* __restrict__ ti,
    const float* __restrict__ t, int U, int I, int nbU,
    const float2* __restrict__ awf,
    const float* __restrict__ ub1, const float* __restrict__ uw2,
    const float* __restrict__ ib1, const float* __restrict__ iw2,
    float* __restrict__ out_u, float* __restrict__ out_i)
{
    extern __shared__ __align__(16) float sm[];
    const int b = blockIdx.x;
    const bool isU = b < nbU;
    const int node0 = (isU ? b : (b - nbU)) * 64;
    const int N = isU ? U : I;
    const float* zB[3];
    if (isU) { zB[0] = tu; zB[1] = tu + (size_t)U * 64; zB[2] = t; }
    else     { zB[0] = ti; zB[1] = ti + (size_t)I * 64; zB[2] = t + (size_t)U * 64; }
    const float* b1 = isU ? ub1 : ib1;
    const float* w2 = isU ? uw2 : iw2;
    const float2* wf = awf + (isU ? 0 : 1024);
    float* out = isU ? out_u : out_i;

    const int tid = threadIdx.x;

#pragma unroll
    for (int r = 0; r < 3; ++r) {
        const float* zr = zB[r];
        float* dst = sm + r * ATT_TILE_F;
        for (int i = tid; i < 64 * 16; i += 128) {
            int row = i >> 4, c4 = i & 15;
            int gr = node0 + row;
            float4 v = make_float4(0.f, 0.f, 0.f, 0.f);
            if (gr < N) v = *reinterpret_cast<const float4*>(zr + (size_t)gr * 64 + c4 * 4);
            *reinterpret_cast<float4*>(dst + row * 68 + c4 * 4) = v;
        }
    }
    __syncthreads();

    const int wid = tid >> 5;
    const int lane = tid & 31;
    const int g = lane >> 2;
    const int t4 = lane & 3;
    float* wl = sm + 3 * ATT_TILE_F;

#pragma unroll
    for (int rel = 0; rel < 3; ++rel) {
        const float* xr0 = sm + rel * ATT_TILE_F + (wid * 16 + g) * 68;
        const float* xr1 = xr0 + 8 * 68;
        float acc[4][4];
#pragma unroll
        for (int nt = 0; nt < 4; ++nt)
#pragma unroll
            for (int i = 0; i < 4; ++i) acc[nt][i] = 0.f;
#pragma unroll
        for (int kt = 0; kt < 8; ++kt) {
            int c0 = kt * 8 + t4;
            unsigned int a0 = tf32c(xr0[c0]);
            unsigned int a1 = tf32c(xr1[c0]);
            unsigned int a2 = tf32c(xr0[c0 + 4]);
            unsigned int a3 = tf32c(xr1[c0 + 4]);
            const float2* wr = wf + kt * 128 + lane;
#pragma unroll
            for (int nt = 0; nt < 4; ++nt) {
                float2 w = wr[nt * 32];
                mma_tf32(acc[nt], a0, a1, a2, a3,
                         __float_as_uint(w.x), __float_as_uint(w.y));
            }
        }
        float s0 = 0.f, s1 = 0.f;
#pragma unroll
        for (int nt = 0; nt < 4; ++nt) {
            int col = nt * 8 + 2 * t4;
            float b1x = b1[col], b1y = b1[col + 1];
            float w2x = w2[col], w2y = w2[col + 1];
            s0 += tanhf(acc[nt][0] + b1x) * w2x + tanhf(acc[nt][1] + b1y) * w2y;
            s1 += tanhf(acc[nt][2] + b1x) * w2x + tanhf(acc[nt][3] + b1y) * w2y;
        }
        s0 += __shfl_xor_sync(0xffffffffu, s0, 1);
        s0 += __shfl_xor_sync(0xffffffffu, s0, 2);
        s1 += __shfl_xor_sync(0xffffffffu, s1, 1);
        s1 += __shfl_xor_sync(0xffffffffu, s1, 2);
        if (t4 == 0) {
            int r0 = wid * 16 + g;
            wl[r0 * 4 + rel] = s0;
            wl[(r0 + 8) * 4 + rel] = s1;
        }
    }
    __syncthreads();

    {
        int row = tid >> 1;
        int gr = node0 + row;
        if (gr < N) {
            float w0 = wl[row * 4 + 0], w1v = wl[row * 4 + 1], w2v = wl[row * 4 + 2];
            float mx = fmaxf(w0, fmaxf(w1v, w2v));
            float e0 = __expf(w0 - mx), e1 = __expf(w1v - mx), e2 = __expf(w2v - mx);
            float inv = 1.0f / (e0 + e1 + e2);
            float beta0 = e0 * inv, beta1 = e1 * inv, beta2 = e2 * inv;
            int hoff = (tid & 1) * 32;
            const float* z0p = sm + 0 * ATT_TILE_F + row * 68 + hoff;
            const float* z1p = sm + 1 * ATT_TILE_F + row * 68 + hoff;
            const float* z2p = sm + 2 * ATT_TILE_F + row * 68 + hoff;
            float* op = out + (size_t)gr * 64 + hoff;
#pragma unroll
            for (int i = 0; i < 8; ++i) {
                float4 A = *reinterpret_cast<const float4*>(z0p + i * 4);
                float4 B = *reinterpret_cast<const float4*>(z1p + i * 4);
                float4 C = *reinterpret_cast<const float4*>(z2p + i * 4);
                float4 o;
                o.x = beta0 * A.x + beta1 * B.x + beta2 * C.x;
                o.y = beta0 * A.y + beta1 * B.y + beta2 * C.y;
                o.z = beta0 * A.z + beta1 * B.z + beta2 * C.z;
                o.w = beta0 * A.w + beta1 * B.w + beta2 * C.w;
                *reinterpret_cast<float4*>(op + i * 4) = o;
            }
        }
    }
}

// ---------------- host launcher ----------------
extern "C" void kernel_launch(void* const* d_in, const int* in_sizes, int n_in,
                              void* d_out, int out_size)
{
    const int*   u2i_idx  = (const int*)  d_in[0];
    const float* u2i_val  = (const float*)d_in[1];
    const int*   u2e_idx  = (const int*)  d_in[2];
    const float* u2e_val  = (const float*)d_in[3];
    const int*   i2e_idx  = (const int*)  d_in[4];
    const float* i2e_val  = (const float*)d_in[5];
    const float* u_feat   = (const float*)d_in[6];
    const float* i_feat   = (const float*)d_in[7];
    const float* u2e_feat = (const float*)d_in[8];
    const float* i2e_feat = (const float*)d_in[9];
    const float* Tw_u2i = (const float*)d_in[10];
    const float* Tb_u2i = (const float*)d_in[11];
    const float* Iw_u2i = (const float*)d_in[12];
    const float* Ib_u2i = (const float*)d_in[13];
    const float* Tw_u2e = (const float*)d_in[14];
    const float* Tb_u2e = (const float*)d_in[15];
    const float* Iw_u2e = (const float*)d_in[16];
    const float* Ib_u2e = (const float*)d_in[17];
    const float* Tw_i2e = (const float*)d_in[18];
    const float* Tb_i2e = (const float*)d_in[19];
    const float* Iw_i2e = (const float*)d_in[20];
    const float* Ib_i2e = (const float*)d_in[21];
    const float* uatt_w1 = (const float*)d_in[22];
    const float* uatt_b1 = (const float*)d_in[23];
    const float* uatt_w2 = (const float*)d_in[24];
    const float* iatt_w1 = (const float*)d_in[25];
    const float* iatt_b1 = (const float*)d_in[26];
    const float* iatt_w2 = (const float*)d_in[27];

    const int U = in_sizes[6] / 64;
    const int I = in_sizes[7] / 64;
    const int E = in_sizes[8] / (2 * 64);
    const int NNZ_UI = in_sizes[1];
    const int NNZ_E  = in_sizes[3] / 2;

    float *tu, *ti, *t, *s;
    float2 *wT, *wI, *awf;
    cudaGetSymbolAddress((void**)&tu, g_tu);
    cudaGetSymbolAddress((void**)&ti, g_ti);
    cudaGetSymbolAddress((void**)&t,  g_t);
    cudaGetSymbolAddress((void**)&s,  g_s);
    cudaGetSymbolAddress((void**)&wT, g_wT);
    cudaGetSymbolAddress((void**)&wI, g_wI);
    cudaGetSymbolAddress((void**)&awf, g_awf);

    float* outp    = (float*)d_out;
    float* out_u   = outp;
    float* out_i   = outp + (size_t)U * 64;
    float* out_u2e = outp + (size_t)(U + I) * 64;
    float* out_i2e = out_u2e + (size_t)2 * E * 64;

    int ns[5]  = {U + E, U + E, I + E, I + E, U + I};
    int rb[6];
    rb[0] = 0;
    for (int i = 0; i < 5; ++i) rb[i + 1] = rb[i] + ns[i];

    pack_weights<<<40, 256>>>(
        Tw_u2e, Iw_u2e, Tw_u2e + 4096, Iw_u2e + 4096,
        Tw_i2e, Iw_i2e, Tw_i2e + 4096, Iw_i2e + 4096,
        Tw_u2i, Iw_u2i, wT, wI);
    pack_att<<<8, 256>>>(uatt_w1, iatt_w1, awf);

    GTab gt;
    {
        const float* xAs[5] = {u_feat, u_feat, i_feat, i_feat, u_feat};
        const float* xBs[5] = {u2e_feat, u2e_feat + (size_t)E * 64,
                               i2e_feat, i2e_feat + (size_t)E * 64, i_feat};
        int gnAs[5] = {U, U, I, I, U};
        const float* Tbs[5] = {Tb_u2e, Tb_u2e + 64, Tb_i2e, Tb_i2e + 64, Tb_u2i};
        const float* Ibs[5] = {Ib_u2e, Ib_u2e + 64, Ib_i2e, Ib_i2e + 64, Ib_u2i};
        float* outAs[5] = {tu, tu + (size_t)U * 64, ti, ti + (size_t)I * 64, t};
        float* outBs[5] = {out_u2e, out_u2e + (size_t)E * 64,
                           out_i2e, out_i2e + (size_t)E * 64, t + (size_t)U * 64};
        gt.off[0] = 0;
        for (int i = 0; i < 5; ++i) {
            gt.c[i].xA = xAs[i]; gt.c[i].xB = xBs[i];
            gt.c[i].nA = gnAs[i]; gt.c[i].n = ns[i];
            gt.c[i].wT = wT + (size_t)i * 2048;
            gt.c[i].wI = wI + (size_t)i * 2048;
            gt.c[i].Tb = Tbs[i]; gt.c[i].Ib = Ibs[i];
            gt.c[i].outA = outAs[i]; gt.c[i].outB = outBs[i];
            gt.c[i].s = s + (size_t)rb[i] * 64;
            gt.off[i + 1] = gt.off[i] + (ns[i] + 63) / 64;
        }
    }
    gcn_gemm_all<<<gt.off[5], 128>>>(gt);

    STab st;
    {
        const int* rws[5] = {u2e_idx, u2e_idx + (size_t)2 * NNZ_E,
                             i2e_idx, i2e_idx + (size_t)2 * NNZ_E, u2i_idx};
        const float* vls[5] = {u2e_val, u2e_val + NNZ_E,
                               i2e_val, i2e_val + NNZ_E, u2i_val};
        int nnzs[5] = {NNZ_E, NNZ_E, NNZ_E, NNZ_E, NNZ_UI};
        int nAs[5]  = {U, U, I, I, U + I};
        float* outAs[5] = {tu, tu + (size_t)U * 64, ti, ti + (size_t)I * 64, t};
        float* outBs[5] = {out_u2e, out_u2e + (size_t)E * 64,
                           out_i2e, out_i2e + (size_t)E * 64, t};
        st.off[0] = 0;
        for (int i = 0; i < 5; ++i) {
            st.c[i].rows = rws[i];
            st.c[i].cols = rws[i] + nnzs[i];
            st.c[i].vals = vls[i];
            st.c[i].nnz = nnzs[i];
            st.c[i].sIn = s + (size_t)rb[i] * 64;
            st.c[i].outA = outAs[i];
            st.c[i].nA = nAs[i];
            st.c[i].outB = outBs[i];
            long long th = ((long long)nnzs[i] + 3) / 4 * 16;
            st.off[i + 1] = st.off[i] + (int)((th + 255) / 256);
        }
    }
    spmm_all<<<st.off[5], 256>>>(st);

    const int smemB = ATT_SMEM_F * 4;
    cudaFuncSetAttribute(rel_att_tc, cudaFuncAttributeMaxDynamicSharedMemorySize, smemB);
    int nbU = (U + 63) / 64, nbI = (I + 63) / 64;
    rel_att_tc<<<nbU + nbI, 128, smemB>>>(
        tu, ti, t, U, I, nbU, awf,
        uatt_b1, uatt_w2, iatt_b1, iatt_w2,
        out_u, out_i);
}